// round 16
// baseline (speedup 1.0000x reference)
#include <cuda_runtime.h>
#include <cuda_fp16.h>
#include <math.h>
#include <stdint.h>

// Problem constants
#define MTOT 2048   // BATCH*SEQ = 32*64
#define NE   4096   // EMBED_DIM
#define KE   4096

// ---------------- scratch (allocation-free: __device__ globals) ----------------
__device__ float g_Q[MTOT * NE];
__device__ float g_K[MTOT * NE];
__device__ float g_V[MTOT * NE];
__device__ float g_G[MTOT * NE];

__device__ __half g_xh[MTOT * NE];
__device__ __half g_ah[MTOT * NE];

// =====================================================================
// helpers
// =====================================================================
__device__ __forceinline__ uint32_t smem_u32(const void* p) {
    uint32_t a;
    asm("{ .reg .u64 t; cvta.to.shared.u64 t, %1; cvt.u32.u64 %0, t; }" : "=r"(a) : "l"(p));
    return a;
}
__device__ __forceinline__ void cp16(uint32_t s, const void* g) {
    asm volatile("cp.async.cg.shared.global [%0], [%1], 16;" :: "r"(s), "l"(g));
}
__device__ __forceinline__ void cp_commit() {
    asm volatile("cp.async.commit_group;" ::: "memory");
}
template <int N>
__device__ __forceinline__ void cp_wait() {
    asm volatile("cp.async.wait_group %0;" :: "n"(N) : "memory");
}
__device__ __forceinline__ void ldm_x4(uint32_t* r, uint32_t a) {
    asm volatile("ldmatrix.sync.aligned.m8n8.x4.shared.b16 {%0,%1,%2,%3}, [%4];"
                 : "=r"(r[0]), "=r"(r[1]), "=r"(r[2]), "=r"(r[3]) : "r"(a));
}
__device__ __forceinline__ void mma4(float* c, const uint32_t* a, uint32_t b0, uint32_t b1) {
    asm volatile("mma.sync.aligned.m16n8k16.row.col.f32.f16.f16.f32 "
                 "{%0,%1,%2,%3}, {%4,%5,%6,%7}, {%8,%9}, {%0,%1,%2,%3};"
                 : "+f"(c[0]), "+f"(c[1]), "+f"(c[2]), "+f"(c[3])
                 : "r"(a[0]), "r"(a[1]), "r"(a[2]), "r"(a[3]), "r"(b0), "r"(b1));
}

// =====================================================================
// fp32 -> fp16 convert (x only; weights convert in-GEMM now)
// =====================================================================
__global__ void conv_h(const float* __restrict__ in, __half* __restrict__ hi, int n4)
{
    int i = blockIdx.x * blockDim.x + threadIdx.x;
    const int str = gridDim.x * blockDim.x;
    for (; i < n4; i += str) {
        float4 v = ((const float4*)in)[i];
        __half2* hp = (__half2*)hi;
        hp[2 * i]     = __half2(__float2half(v.x), __float2half(v.y));
        hp[2 * i + 1] = __half2(__float2half(v.z), __float2half(v.w));
    }
}

// =====================================================================
// gemm_f: 1-term fp16 GEMM, BK=64. A: fp16 via cp.async.
// B: fp32 weights loaded with LDG.128, converted in-register, STS fp16
//    (two 32-reg halves per stage, latency hidden behind MMA blocks).
// CTA tile 128x256, 8 warps (2m x 4n), warp tile 64x64, 3 stages.
// z selects W/bias/C; z==sigz -> sigmoid epilogue.
// =====================================================================
#define RS64 144
#define PB64 18432        // A tile = 128*144 bytes
#define STG64 55296       // + B tile 256*144 bytes
#define GSMEM (3 * STG64) // 165888 bytes

__global__ __launch_bounds__(256, 1) void gemm_f(
    const __half* __restrict__ Ahp,
    const float* __restrict__ W0, const float* __restrict__ W1,
    const float* __restrict__ W2, const float* __restrict__ W3,
    const float* __restrict__ b0p, const float* __restrict__ b1p,
    const float* __restrict__ b2p, const float* __restrict__ b3p,
    float* C0, float* C1, float* C2, float* C3, int sigz)
{
    extern __shared__ char smem[];
    const uint32_t sb = smem_u32(smem);
    const int tid = threadIdx.x, z = blockIdx.z;
    const bool dosig = (z == sigz);

    const float* Wf   = (z == 0) ? W0 : (z == 1) ? W1 : (z == 2) ? W2 : W3;
    const float* bias = (z == 0) ? b0p : (z == 1) ? b1p : (z == 2) ? b2p : b3p;
    float*       C    = (z == 0) ? C0  : (z == 1) ? C1  : (z == 2) ? C2  : C3;

    const int bm = blockIdx.y * 128;
    const int bn = blockIdx.x * 256;
    const size_t aoff = (size_t)bm * KE;
    const float* Wbase = Wf + (size_t)bn * KE;

    const int lane = tid & 31, wid = tid >> 5;
    const int wm = wid >> 2, wn = wid & 3;
    const int mA = lane >> 3, rA = lane & 7;

    // per-thread B chunk mapping (8 chunks of 8 halves)
    const int brow0 = tid >> 3, bch = tid & 7;   // +u*32 rows per u

    uint32_t offA[4], offB[4];
#pragma unroll
    for (int mi = 0; mi < 4; mi++)
        offA[mi] = (uint32_t)((wm * 64 + mi * 16 + (mA & 1) * 8 + rA) * RS64 + (mA >> 1) * 16);
#pragma unroll
    for (int njp = 0; njp < 4; njp++)
        offB[njp] = (uint32_t)(PB64 + (wn * 64 + njp * 16 + (mA >> 1) * 8 + rA) * RS64 + (mA & 1) * 16);

    float acc[4][8][4];
#pragma unroll
    for (int mi = 0; mi < 4; mi++)
#pragma unroll
        for (int nj = 0; nj < 8; nj++)
#pragma unroll
            for (int r = 0; r < 4; r++) acc[mi][nj][r] = 0.f;

    // A loader (cp.async, fp16)
    auto loadA = [&](int p, int kt) {
        const uint32_t s = sb + (uint32_t)p * STG64;
#pragma unroll
        for (int u = 0; u < 4; u++) {
            const int c = tid + u * 256;
            const int row = c >> 3, ch = c & 7;
            cp16(s + (uint32_t)(row * RS64 + ch * 16),
                 Ahp + aoff + (size_t)row * KE + kt + ch * 8);
        }
        cp_commit();
    };

    // B half-loaders: LDG fp32 (half = 0/1 -> u 0..3 / 4..7)
    auto ldgB = [&](int kt, int half, float4* st) {
#pragma unroll
        for (int u = 0; u < 4; u++) {
            const int row = brow0 + (u + half * 4) * 32;
            const float* p = Wbase + (size_t)row * KE + kt + bch * 8;
            st[2 * u]     = *(const float4*)p;
            st[2 * u + 1] = *(const float4*)(p + 4);
        }
    };
    auto stsB = [&](int p, int half, const float4* st) {
#pragma unroll
        for (int u = 0; u < 4; u++) {
            const int row = brow0 + (u + half * 4) * 32;
            __half2 h[4];
            h[0] = __floats2half2_rn(st[2 * u].x,     st[2 * u].y);
            h[1] = __floats2half2_rn(st[2 * u].z,     st[2 * u].w);
            h[2] = __floats2half2_rn(st[2 * u + 1].x, st[2 * u + 1].y);
            h[3] = __floats2half2_rn(st[2 * u + 1].z, st[2 * u + 1].w);
            *(uint4*)(smem + (size_t)p * STG64 + PB64 + row * RS64 + bch * 16) = *(uint4*)h;
        }
    };

    // ---- prologue: B stages 0,1 (LDG+cvt+STS), A stages 0,1 (cp.async) ----
    {
        float4 st[8];
        ldgB(0, 0, st);  stsB(0, 0, st);
        ldgB(0, 1, st);  stsB(0, 1, st);
        ldgB(64, 0, st); stsB(1, 0, st);
        ldgB(64, 1, st); stsB(1, 1, st);
    }
    loadA(0, 0);
    loadA(1, 64);

    auto mmab = [&](uint32_t fa[4][4], uint32_t fb[4][4]) {
#pragma unroll
        for (int njp = 0; njp < 4; njp++)
#pragma unroll
            for (int mi = 0; mi < 4; mi++) {
                mma4(acc[mi][2 * njp],     fa[mi], fb[njp][0], fb[njp][1]);
                mma4(acc[mi][2 * njp + 1], fa[mi], fb[njp][2], fb[njp][3]);
            }
    };

    const int p2 = (wid & 1) * 2;   // warp-parity k-stagger
    const uint32_t kb0 = (uint32_t)(((0 + p2) & 3) * 32);
    const uint32_t kb1 = (uint32_t)(((1 + p2) & 3) * 32);
    const uint32_t kb2 = (uint32_t)(((2 + p2) & 3) * 32);
    const uint32_t kb3 = (uint32_t)(((3 + p2) & 3) * 32);

    const int NST = KE / 64;  // 64
    for (int i = 0; i < NST; i++) {
        if (i >= NST - 2) cp_wait<0>();
        else              cp_wait<1>();
        __syncthreads();

        const uint32_t s = sb + (uint32_t)(i % 3) * STG64;
        const bool nxt = (i + 2 < NST);
        const int pn = (i + 2) % 3;
        const int ktn = (i + 2) * 64;

        float4 st[8];
        uint32_t fA[4][4], fB[4][4];

        if (nxt) ldgB(ktn, 0, st);          // LDG half1 (latency covered by MMA kb0)

#pragma unroll
        for (int mi = 0; mi < 4; mi++)    ldm_x4(fA[mi], s + offA[mi] + kb0);
#pragma unroll
        for (int njp = 0; njp < 4; njp++) ldm_x4(fB[njp], s + offB[njp] + kb0);
        mmab(fA, fB);

        if (nxt) { stsB(pn, 0, st); ldgB(ktn, 1, st); }

#pragma unroll
        for (int mi = 0; mi < 4; mi++)    ldm_x4(fA[mi], s + offA[mi] + kb1);
#pragma unroll
        for (int njp = 0; njp < 4; njp++) ldm_x4(fB[njp], s + offB[njp] + kb1);
        mmab(fA, fB);

        if (nxt) loadA(pn, ktn);            // cp.async + commit

#pragma unroll
        for (int mi = 0; mi < 4; mi++)    ldm_x4(fA[mi], s + offA[mi] + kb2);
#pragma unroll
        for (int njp = 0; njp < 4; njp++) ldm_x4(fB[njp], s + offB[njp] + kb2);
        mmab(fA, fB);

        if (nxt) stsB(pn, 1, st);

#pragma unroll
        for (int mi = 0; mi < 4; mi++)    ldm_x4(fA[mi], s + offA[mi] + kb3);
#pragma unroll
        for (int njp = 0; njp < 4; njp++) ldm_x4(fB[njp], s + offB[njp] + kb3);
        mmab(fA, fB);
    }

    // epilogue (sigmoid if gamma)
    const int g = lane >> 2, t4 = lane & 3;
#pragma unroll
    for (int mi = 0; mi < 4; mi++) {
#pragma unroll
        for (int nj = 0; nj < 8; nj++) {
            const int row = bm + wm * 64 + mi * 16 + g;
            const int col = bn + wn * 64 + nj * 8 + 2 * t4;
            const float bb0 = bias[col], bb1 = bias[col + 1];
            float v0 = acc[mi][nj][0] + bb0, v1 = acc[mi][nj][1] + bb1;
            float v2 = acc[mi][nj][2] + bb0, v3 = acc[mi][nj][3] + bb1;
            if (dosig) {
                v0 = 1.f / (1.f + expf(-v0)); v1 = 1.f / (1.f + expf(-v1));
                v2 = 1.f / (1.f + expf(-v2)); v3 = 1.f / (1.f + expf(-v3));
            }
            *(float2*)(C + (size_t)row * NE + col)       = make_float2(v0, v1);
            *(float2*)(C + (size_t)(row + 8) * NE + col) = make_float2(v2, v3);
        }
    }
}

// =====================================================================
// attn3: 384 threads, 2 CTAs/SM. fp16 Q/K/V/S smem, fp32 gc/gi.
// RoPE fused into load. V overlaid on Q post-score.
// O-phase uses a cost-balanced static chunk->warp map.
// =====================================================================
#define SQH 136
#define SKH 68
#define SGD 132
#define SGI 68
#define SSH 68
#define A3_OKT 17408
#define A3_OGC 34816
#define A3_OGI 68608
#define A3_OS  103424
#define A3SMEM 112128

__global__ __launch_bounds__(384, 2) void attn3(
    const float* __restrict__ Q, const float* __restrict__ K,
    const float* __restrict__ V, const float* __restrict__ G,
    const float* __restrict__ t, __half* __restrict__ OH)
{
    extern __shared__ char smc[];
    __half* sQV  = (__half*)(smc);
    __half* sKT  = (__half*)(smc + A3_OKT);
    float*  sGc  = (float*)(smc + A3_OGC);
    float*  sGiT = (float*)(smc + A3_OGI);
    __half* sS   = (__half*)(smc + A3_OS);
    const uint32_t sb = smem_u32(smc);

    const int bh = blockIdx.x;
    const int b  = bh >> 5, h = bh & 31;
    const int tid = threadIdx.x;
    const size_t base = ((size_t)b * 64) * 4096 + (size_t)h * 128;

    // ---- G via cp.async (fp32) ----
    for (int c = tid; c < 2048; c += 384) {
        const int row = c >> 5, ch = c & 31;
        cp16(sb + A3_OGC + (uint32_t)(row * 528 + ch * 16),
             G + base + (size_t)row * 4096 + ch * 4);
    }
    cp_commit();

    // ---- Q,K load + fused RoPE (shared angle), store fp16 ----
    const float LN1E4_64 = 0.14391156531879916f;
    for (int i = tid; i < 4096; i += 384) {
        const int s = i >> 6, q = i & 63;
        const float invf = expf(-(float)s * LN1E4_64);
        const float ang  = t[q] * invf;
        const float cs = cosf(ang), sn = sinf(ang);
        float a, b2;
        a = Q[base + (size_t)s * 4096 + q]; b2 = Q[base + (size_t)s * 4096 + q + 64];
        sQV[s * SQH + q]      = __float2half(a * cs - b2 * sn);
        sQV[s * SQH + q + 64] = __float2half(b2 * cs + a * sn);
        a = K[base + (size_t)s * 4096 + q]; b2 = K[base + (size_t)s * 4096 + q + 64];
        sKT[q * SKH + s]        = __float2half(a * cs - b2 * sn);
        sKT[(q + 64) * SKH + s] = __float2half(b2 * cs + a * sn);
    }
    cp_wait<0>();
    __syncthreads();

    // ---- cumprod (fp32), gi transposed ----
    if (tid < 128) {
        const int d = tid;
        float run = 1.f;
        for (int s = 0; s < 64; s++) {
            run *= sGc[s * SGD + d];
            sGc[s * SGD + d]  = run;
            sGiT[d * SGI + s] = 1.f / run;
        }
    }
    __syncthreads();

    // ---- score phase: 10 active warps on lower-triangle 16x16 tiles ----
    {
        const int w = tid >> 5, lane = tid & 31;
        int wq = 0;
        if (w >= 1) wq = 1;
        if (w >= 3) wq = 2;
        if (w >= 6) wq = 3;
        const int wk = w - (wq * (wq + 1)) / 2;

        if (w < 10) {
            const int lq = lane >> 2, lk = lane & 3;
            const int q0 = wq * 16 + lq * 2;
            const int k0 = wk * 16 + lk * 4;
            float acc[2][4] = {{0,0,0,0},{0,0,0,0}};
            float dac[2][4] = {{0,0,0,0},{0,0,0,0}};

#pragma unroll 2
            for (int kk = 0; kk < 128; kk += 4) {
                float2 q0a = __half22float2(*(const __half2*)&sQV[q0 * SQH + kk]);
                float2 q0b = __half22float2(*(const __half2*)&sQV[q0 * SQH + kk + 2]);
                float2 q1a = __half22float2(*(const __half2*)&sQV[(q0 + 1) * SQH + kk]);
                float2 q1b = __half22float2(*(const __half2*)&sQV[(q0 + 1) * SQH + kk + 2]);
                const float qv0[4] = {q0a.x, q0a.y, q0b.x, q0b.y};
                const float qv1[4] = {q1a.x, q1a.y, q1b.x, q1b.y};
                float gq0[4], gq1[4];
                *(float4*)gq0 = *(const float4*)&sGc[q0 * SGD + kk];
                *(float4*)gq1 = *(const float4*)&sGc[(q0 + 1) * SGD + kk];
                float kv[4][4], gi[4][4];
#pragma unroll
                for (int r = 0; r < 4; r++) {
                    float2 ka = __half22float2(*(const __half2*)&sKT[(kk + r) * SKH + k0]);
                    float2 kb = __half22float2(*(const __half2*)&sKT[(kk + r) * SKH + k0 + 2]);
                    kv[r][0] = ka.x; kv[r][1] = ka.y; kv[r][2] = kb.x; kv[r][3] = kb.y;
                    *(float4*)gi[r] = *(const float4*)&sGiT[(kk + r) * SGI + k0];
                }
#pragma unroll
                for (int r = 0; r < 4; r++)
#pragma unroll
                    for (int j = 0; j < 4; j++) {
                        acc[0][j] = fmaf(qv0[r], kv[r][j], acc[0][j]);
                        acc[1][j] = fmaf(qv1[r], kv[r][j], acc[1][j]);
                        dac[0][j] = fmaf(gq0[r], gi[r][j], dac[0][j]);
                        dac[1][j] = fmaf(gq1[r], gi[r][j], dac[1][j]);
                    }
            }
#pragma unroll
            for (int i = 0; i < 2; i++) {
                const int qi = q0 + i;
                float v[4];
#pragma unroll
                for (int j = 0; j < 4; j++) {
                    const int kj = k0 + j;
                    v[j] = (kj <= qi) ? acc[i][j] * dac[i][j] * (1.0f / 128.0f) : 0.f;
                }
                *(__half2*)&sS[qi * SSH + k0]     = __floats2half2_rn(v[0], v[1]);
                *(__half2*)&sS[qi * SSH + k0 + 2] = __floats2half2_rn(v[2], v[3]);
            }
        }
    }
    __syncthreads();

    // ---- V load (fp32 -> fp16), overlaid on Q buffer ----
    for (int c = tid; c < 2048; c += 384) {
        const int row = c >> 5, ch = c & 31;
        float4 v = *(const float4*)(V + base + (size_t)row * 4096 + ch * 4);
        __half2* dst = (__half2*)&sQV[row * SQH + ch * 4];
        dst[0] = __floats2half2_rn(v.x, v.y);
        dst[1] = __floats2half2_rn(v.z, v.w);
    }
    __syncthreads();

    // ---- O = S @ V: cost-balanced chunk map (chunk c costs c+1) ----
    //   warp w handles chunk 15-w; warps 8..11 additionally handle w-8.
    {
        const int w = tid >> 5, lane = tid & 31;
        const int d0 = lane * 4;
        int clist[2];
        clist[0] = 15 - w;
        clist[1] = (w >= 8) ? (w - 8) : -1;
#pragma unroll
        for (int ci = 0; ci < 2; ci++) {
            const int c = clist[ci];
            if (c < 0) continue;
#pragma unroll
            for (int qq = 0; qq < 4; qq++) {
                const int q = c * 4 + qq;
                float a0 = 0.f, a1 = 0.f, a2 = 0.f, a3 = 0.f;
                for (int kq = 0; kq <= c; kq++) {
                    float2 sa = __half22float2(*(const __half2*)&sS[q * SSH + kq * 4]);
                    float2 sc = __half22float2(*(const __half2*)&sS[q * SSH + kq * 4 + 2]);
                    const float sv[4] = {sa.x, sa.y, sc.x, sc.y};
#pragma unroll
                    for (int r = 0; r < 4; r++) {
                        float2 va = __half22float2(*(const __half2*)&sQV[(kq * 4 + r) * SQH + d0]);
                        float2 vb = __half22float2(*(const __half2*)&sQV[(kq * 4 + r) * SQH + d0 + 2]);
                        a0 = fmaf(sv[r], va.x, a0);
                        a1 = fmaf(sv[r], va.y, a1);
                        a2 = fmaf(sv[r], vb.x, a2);
                        a3 = fmaf(sv[r], vb.y, a3);
                    }
                }
                const size_t go = base + (size_t)q * 4096 + d0;
                *(__half2*)(OH + go)     = __floats2half2_rn(a0, a1);
                *(__half2*)(OH + go + 2) = __floats2half2_rn(a2, a3);
            }
        }
    }
}

// =====================================================================
// launch
// =====================================================================
extern "C" void kernel_launch(void* const* d_in, const int* in_sizes, int n_in,
                              void* d_out, int out_size)
{
    const float* x  = (const float*)d_in[0];
    const float* t  = (const float*)d_in[1];
    const float* Wq = (const float*)d_in[2];
    const float* bq = (const float*)d_in[3];
    const float* Wk = (const float*)d_in[4];
    const float* bk = (const float*)d_in[5];
    const float* Wv = (const float*)d_in[6];
    const float* bv = (const float*)d_in[7];
    const float* Wd = (const float*)d_in[8];
    const float* bd = (const float*)d_in[9];
    const float* Wo = (const float*)d_in[10];
    const float* bo = (const float*)d_in[11];
    float* out = (float*)d_out;

    float *Qb, *Kb, *Vb, *Gb;
    __half *xh, *ah;
    cudaGetSymbolAddress((void**)&Qb, g_Q);
    cudaGetSymbolAddress((void**)&Kb, g_K);
    cudaGetSymbolAddress((void**)&Vb, g_V);
    cudaGetSymbolAddress((void**)&Gb, g_G);
    cudaGetSymbolAddress((void**)&xh, g_xh);
    cudaGetSymbolAddress((void**)&ah, g_ah);

    const int n4x = MTOT * NE / 4;
    conv_h<<<2048, 256>>>(x, xh, n4x);

    cudaFuncSetAttribute(gemm_f, cudaFuncAttributeMaxDynamicSharedMemorySize, GSMEM);

    // merged Q/K/V/gamma projections (weights converted in-GEMM; z=3 -> sigmoid)
    gemm_f<<<dim3(NE / 256, MTOT / 128, 4), 256, GSMEM>>>(
        xh, Wq, Wk, Wv, Wd, bq, bk, bv, bd, Qb, Kb, Vb, Gb, /*sigz=*/3);

    // fused attention (2 CTAs/SM, writes fp16 plane directly)
    cudaFuncSetAttribute(attn3, cudaFuncAttributeMaxDynamicSharedMemorySize, A3SMEM);
    attn3<<<1024, 384, A3SMEM>>>(Qb, Kb, Vb, Gb, t, ah);

    // output projection
    gemm_f<<<dim3(NE / 256, MTOT / 128, 1), 256, GSMEM>>>(
        ah, Wo, Wo, Wo, Wo, bo, bo, bo, bo, out, out, out, out, /*sigz=*/-1);
}

// round 17
// speedup vs baseline: 1.1918x; 1.1918x over previous
#include <cuda_runtime.h>
#include <cuda_fp16.h>
#include <math.h>
#include <stdint.h>

// Problem constants
#define MTOT 2048   // BATCH*SEQ = 32*64
#define NE   4096   // EMBED_DIM
#define KE   4096
#define WSL  16777216ull   // elements per weight slot (4096*4096)

// ---------------- scratch (allocation-free: __device__ globals) ----------------
__device__ float g_Q[MTOT * NE];
__device__ float g_K[MTOT * NE];
__device__ float g_V[MTOT * NE];
__device__ float g_G[MTOT * NE];

__device__ __half g_xh[MTOT * NE];
__device__ __half g_ah[MTOT * NE];
__device__ __half g_wh[5 * WSL];   // slots: Wq,Wk,Wv,Wd,Wo (fp16)

// =====================================================================
// helpers
// =====================================================================
__device__ __forceinline__ uint32_t smem_u32(const void* p) {
    uint32_t a;
    asm("{ .reg .u64 t; cvta.to.shared.u64 t, %1; cvt.u32.u64 %0, t; }" : "=r"(a) : "l"(p));
    return a;
}
__device__ __forceinline__ void cp16(uint32_t s, const void* g) {
    asm volatile("cp.async.cg.shared.global [%0], [%1], 16;" :: "r"(s), "l"(g));
}
__device__ __forceinline__ void cp_commit() {
    asm volatile("cp.async.commit_group;" ::: "memory");
}
template <int N>
__device__ __forceinline__ void cp_wait() {
    asm volatile("cp.async.wait_group %0;" :: "n"(N) : "memory");
}
__device__ __forceinline__ void ldm_x4(uint32_t* r, uint32_t a) {
    asm volatile("ldmatrix.sync.aligned.m8n8.x4.shared.b16 {%0,%1,%2,%3}, [%4];"
                 : "=r"(r[0]), "=r"(r[1]), "=r"(r[2]), "=r"(r[3]) : "r"(a));
}
__device__ __forceinline__ void mma4(float* c, const uint32_t* a, uint32_t b0, uint32_t b1) {
    asm volatile("mma.sync.aligned.m16n8k16.row.col.f32.f16.f16.f32 "
                 "{%0,%1,%2,%3}, {%4,%5,%6,%7}, {%8,%9}, {%0,%1,%2,%3};"
                 : "+f"(c[0]), "+f"(c[1]), "+f"(c[2]), "+f"(c[3])
                 : "r"(a[0]), "r"(a[1]), "r"(a[2]), "r"(a[3]), "r"(b0), "r"(b1));
}

// =====================================================================
// fp32 -> fp16 converts (R14-verified)
// =====================================================================
__global__ void conv_h(const float* __restrict__ in, __half* __restrict__ hi, int n4)
{
    int i = blockIdx.x * blockDim.x + threadIdx.x;
    const int str = gridDim.x * blockDim.x;
    for (; i < n4; i += str) {
        float4 v = ((const float4*)in)[i];
        __half2* hp = (__half2*)hi;
        hp[2 * i]     = __half2(__float2half(v.x), __float2half(v.y));
        hp[2 * i + 1] = __half2(__float2half(v.z), __float2half(v.w));
    }
}

__global__ void conv_w5(const float* __restrict__ w0, const float* __restrict__ w1,
                        const float* __restrict__ w2, const float* __restrict__ w3,
                        const float* __restrict__ w4, __half* __restrict__ whb, int n4w)
{
    int i = blockIdx.x * blockDim.x + threadIdx.x;
    const int str = gridDim.x * blockDim.x;
    const int tot = 5 * n4w;
    for (; i < tot; i += str) {
        const int slot = i / n4w;
        const int j = i - slot * n4w;
        const float* in = (slot == 0) ? w0 : (slot == 1) ? w1 : (slot == 2) ? w2
                        : (slot == 3) ? w3 : w4;
        float4 v = ((const float4*)in)[j];
        __half2* hp = (__half2*)(whb + (size_t)slot * WSL);
        hp[2 * j]     = __half2(__float2half(v.x), __float2half(v.y));
        hp[2 * j + 1] = __half2(__float2half(v.z), __float2half(v.w));
    }
}

// =====================================================================
// gemm_f: 1-term fp16 GEMM, BK=64, cp.async A+B (R14-verified, 66% tensor)
// =====================================================================
#define RS64 144
#define PB64 18432
#define STG64 55296
#define GSMEM (3 * STG64) // 165888 bytes

__global__ __launch_bounds__(256, 1) void gemm_f(
    const __half* __restrict__ Ahp, const __half* __restrict__ Whp,
    const float* __restrict__ b0p, const float* __restrict__ b1p,
    const float* __restrict__ b2p, const float* __restrict__ b3p,
    float* C0, float* C1, float* C2, float* C3, int sigz)
{
    extern __shared__ char smem[];
    const uint32_t sb = smem_u32(smem);
    const int tid = threadIdx.x, z = blockIdx.z;
    const bool dosig = (z == sigz);

    const __half* Wh = Whp + (size_t)z * WSL;
    const float* bias = (z == 0) ? b0p : (z == 1) ? b1p : (z == 2) ? b2p : b3p;
    float*       C    = (z == 0) ? C0  : (z == 1) ? C1  : (z == 2) ? C2  : C3;

    const int bm = blockIdx.y * 128;
    const int bn = blockIdx.x * 256;
    const size_t aoff = (size_t)bm * KE;
    const size_t boff = (size_t)bn * KE;

    const int lane = tid & 31, wid = tid >> 5;
    const int wm = wid >> 2, wn = wid & 3;
    const int mA = lane >> 3, rA = lane & 7;

    uint32_t offA[4], offB[4];
#pragma unroll
    for (int mi = 0; mi < 4; mi++)
        offA[mi] = (uint32_t)((wm * 64 + mi * 16 + (mA & 1) * 8 + rA) * RS64 + (mA >> 1) * 16);
#pragma unroll
    for (int njp = 0; njp < 4; njp++)
        offB[njp] = (uint32_t)(PB64 + (wn * 64 + njp * 16 + (mA >> 1) * 8 + rA) * RS64 + (mA & 1) * 16);

    float acc[4][8][4];
#pragma unroll
    for (int mi = 0; mi < 4; mi++)
#pragma unroll
        for (int nj = 0; nj < 8; nj++)
#pragma unroll
            for (int r = 0; r < 4; r++) acc[mi][nj][r] = 0.f;

    auto load64 = [&](int p, int kt) {
        const uint32_t s = sb + (uint32_t)p * STG64;
#pragma unroll
        for (int u = 0; u < 4; u++) {
            const int c = tid + u * 256;
            const int row = c >> 3, ch = c & 7;
            cp16(s + (uint32_t)(row * RS64 + ch * 16),
                 Ahp + aoff + (size_t)row * KE + kt + ch * 8);
        }
#pragma unroll
        for (int u = 0; u < 8; u++) {
            const int c = tid + u * 256;
            const int row = c >> 3, ch = c & 7;
            cp16(s + PB64 + (uint32_t)(row * RS64 + ch * 16),
                 Wh + boff + (size_t)row * KE + kt + ch * 8);
        }
        cp_commit();
    };

    auto mmab = [&](uint32_t fa[4][4], uint32_t fb[4][4]) {
#pragma unroll
        for (int njp = 0; njp < 4; njp++)
#pragma unroll
            for (int mi = 0; mi < 4; mi++) {
                mma4(acc[mi][2 * njp],     fa[mi], fb[njp][0], fb[njp][1]);
                mma4(acc[mi][2 * njp + 1], fa[mi], fb[njp][2], fb[njp][3]);
            }
    };

    const int p2 = (wid & 1) * 2;
    const uint32_t kb0 = (uint32_t)(((0 + p2) & 3) * 32);
    const uint32_t kb1 = (uint32_t)(((1 + p2) & 3) * 32);
    const uint32_t kb2 = (uint32_t)(((2 + p2) & 3) * 32);
    const uint32_t kb3 = (uint32_t)(((3 + p2) & 3) * 32);

    load64(0, 0);
    load64(1, 64);

    const int NST = KE / 64;
    for (int i = 0; i < NST; i++) {
        if (i >= NST - 2) cp_wait<0>();
        else              cp_wait<1>();
        __syncthreads();

        const uint32_t s = sb + (uint32_t)(i % 3) * STG64;
        uint32_t fA[2][4][4], fB[2][4][4];

#pragma unroll
        for (int mi = 0; mi < 4; mi++)    ldm_x4(fA[0][mi], s + offA[mi] + kb0);
#pragma unroll
        for (int njp = 0; njp < 4; njp++) ldm_x4(fB[0][njp], s + offB[njp] + kb0);
#pragma unroll
        for (int mi = 0; mi < 4; mi++)    ldm_x4(fA[1][mi], s + offA[mi] + kb1);
#pragma unroll
        for (int njp = 0; njp < 4; njp++) ldm_x4(fB[1][njp], s + offB[njp] + kb1);

        mmab(fA[0], fB[0]);

        if (i + 2 < NST) load64((i + 2) % 3, (i + 2) * 64);

#pragma unroll
        for (int mi = 0; mi < 4; mi++)    ldm_x4(fA[0][mi], s + offA[mi] + kb2);
#pragma unroll
        for (int njp = 0; njp < 4; njp++) ldm_x4(fB[0][njp], s + offB[njp] + kb2);

        mmab(fA[1], fB[1]);

#pragma unroll
        for (int mi = 0; mi < 4; mi++)    ldm_x4(fA[1][mi], s + offA[mi] + kb3);
#pragma unroll
        for (int njp = 0; njp < 4; njp++) ldm_x4(fB[1][njp], s + offB[njp] + kb3);

        mmab(fA[0], fB[0]);
        mmab(fA[1], fB[1]);
    }

    const int g = lane >> 2, t4 = lane & 3;
#pragma unroll
    for (int mi = 0; mi < 4; mi++) {
#pragma unroll
        for (int nj = 0; nj < 8; nj++) {
            const int row = bm + wm * 64 + mi * 16 + g;
            const int col = bn + wn * 64 + nj * 8 + 2 * t4;
            const float bb0 = bias[col], bb1 = bias[col + 1];
            float v0 = acc[mi][nj][0] + bb0, v1 = acc[mi][nj][1] + bb1;
            float v2 = acc[mi][nj][2] + bb0, v3 = acc[mi][nj][3] + bb1;
            if (dosig) {
                v0 = 1.f / (1.f + expf(-v0)); v1 = 1.f / (1.f + expf(-v1));
                v2 = 1.f / (1.f + expf(-v2)); v3 = 1.f / (1.f + expf(-v3));
            }
            *(float2*)(C + (size_t)row * NE + col)       = make_float2(v0, v1);
            *(float2*)(C + (size_t)(row + 8) * NE + col) = make_float2(v2, v3);
        }
    }
}

// =====================================================================
// attn3: 384 threads, 2 CTAs/SM. fp16 Q/K/V/S smem, fp32 gc/gi.
// RoPE fused into load. V overlaid on Q post-score.
// O-phase: cost-balanced static chunk->warp map.
// =====================================================================
#define SQH 136
#define SKH 68
#define SGD 132
#define SGI 68
#define SSH 68
#define A3_OKT 17408
#define A3_OGC 34816
#define A3_OGI 68608
#define A3_OS  103424
#define A3SMEM 112128

__global__ __launch_bounds__(384, 2) void attn3(
    const float* __restrict__ Q, const float* __restrict__ K,
    const float* __restrict__ V, const float* __restrict__ G,
    const float* __restrict__ t, __half* __restrict__ OH)
{
    extern __shared__ char smc[];
    __half* sQV  = (__half*)(smc);
    __half* sKT  = (__half*)(smc + A3_OKT);
    float*  sGc  = (float*)(smc + A3_OGC);
    float*  sGiT = (float*)(smc + A3_OGI);
    __half* sS   = (__half*)(smc + A3_OS);
    const uint32_t sb = smem_u32(smc);

    const int bh = blockIdx.x;
    const int b  = bh >> 5, h = bh & 31;
    const int tid = threadIdx.x;
    const size_t base = ((size_t)b * 64) * 4096 + (size_t)h * 128;

    // ---- G via cp.async (fp32) ----
    for (int c = tid; c < 2048; c += 384) {
        const int row = c >> 5, ch = c & 31;
        cp16(sb + A3_OGC + (uint32_t)(row * 528 + ch * 16),
             G + base + (size_t)row * 4096 + ch * 4);
    }
    cp_commit();

    // ---- Q,K load + fused RoPE (shared angle), store fp16 ----
    const float LN1E4_64 = 0.14391156531879916f;
    for (int i = tid; i < 4096; i += 384) {
        const int s = i >> 6, q = i & 63;
        const float invf = expf(-(float)s * LN1E4_64);
        const float ang  = t[q] * invf;
        const float cs = cosf(ang), sn = sinf(ang);
        float a, b2;
        a = Q[base + (size_t)s * 4096 + q]; b2 = Q[base + (size_t)s * 4096 + q + 64];
        sQV[s * SQH + q]      = __float2half(a * cs - b2 * sn);
        sQV[s * SQH + q + 64] = __float2half(b2 * cs + a * sn);
        a = K[base + (size_t)s * 4096 + q]; b2 = K[base + (size_t)s * 4096 + q + 64];
        sKT[q * SKH + s]        = __float2half(a * cs - b2 * sn);
        sKT[(q + 64) * SKH + s] = __float2half(b2 * cs + a * sn);
    }
    cp_wait<0>();
    __syncthreads();

    // ---- cumprod (fp32), gi transposed ----
    if (tid < 128) {
        const int d = tid;
        float run = 1.f;
        for (int s = 0; s < 64; s++) {
            run *= sGc[s * SGD + d];
            sGc[s * SGD + d]  = run;
            sGiT[d * SGI + s] = 1.f / run;
        }
    }
    __syncthreads();

    // ---- score phase: 10 active warps on lower-triangle 16x16 tiles ----
    {
        const int w = tid >> 5, lane = tid & 31;
        int wq = 0;
        if (w >= 1) wq = 1;
        if (w >= 3) wq = 2;
        if (w >= 6) wq = 3;
        const int wk = w - (wq * (wq + 1)) / 2;

        if (w < 10) {
            const int lq = lane >> 2, lk = lane & 3;
            const int q0 = wq * 16 + lq * 2;
            const int k0 = wk * 16 + lk * 4;
            float acc[2][4] = {{0,0,0,0},{0,0,0,0}};
            float dac[2][4] = {{0,0,0,0},{0,0,0,0}};

#pragma unroll 2
            for (int kk = 0; kk < 128; kk += 4) {
                float2 q0a = __half22float2(*(const __half2*)&sQV[q0 * SQH + kk]);
                float2 q0b = __half22float2(*(const __half2*)&sQV[q0 * SQH + kk + 2]);
                float2 q1a = __half22float2(*(const __half2*)&sQV[(q0 + 1) * SQH + kk]);
                float2 q1b = __half22float2(*(const __half2*)&sQV[(q0 + 1) * SQH + kk + 2]);
                const float qv0[4] = {q0a.x, q0a.y, q0b.x, q0b.y};
                const float qv1[4] = {q1a.x, q1a.y, q1b.x, q1b.y};
                float gq0[4], gq1[4];
                *(float4*)gq0 = *(const float4*)&sGc[q0 * SGD + kk];
                *(float4*)gq1 = *(const float4*)&sGc[(q0 + 1) * SGD + kk];
                float kv[4][4], gi[4][4];
#pragma unroll
                for (int r = 0; r < 4; r++) {
                    float2 ka = __half22float2(*(const __half2*)&sKT[(kk + r) * SKH + k0]);
                    float2 kb = __half22float2(*(const __half2*)&sKT[(kk + r) * SKH + k0 + 2]);
                    kv[r][0] = ka.x; kv[r][1] = ka.y; kv[r][2] = kb.x; kv[r][3] = kb.y;
                    *(float4*)gi[r] = *(const float4*)&sGiT[(kk + r) * SGI + k0];
                }
#pragma unroll
                for (int r = 0; r < 4; r++)
#pragma unroll
                    for (int j = 0; j < 4; j++) {
                        acc[0][j] = fmaf(qv0[r], kv[r][j], acc[0][j]);
                        acc[1][j] = fmaf(qv1[r], kv[r][j], acc[1][j]);
                        dac[0][j] = fmaf(gq0[r], gi[r][j], dac[0][j]);
                        dac[1][j] = fmaf(gq1[r], gi[r][j], dac[1][j]);
                    }
            }
#pragma unroll
            for (int i = 0; i < 2; i++) {
                const int qi = q0 + i;
                float v[4];
#pragma unroll
                for (int j = 0; j < 4; j++) {
                    const int kj = k0 + j;
                    v[j] = (kj <= qi) ? acc[i][j] * dac[i][j] * (1.0f / 128.0f) : 0.f;
                }
                *(__half2*)&sS[qi * SSH + k0]     = __floats2half2_rn(v[0], v[1]);
                *(__half2*)&sS[qi * SSH + k0 + 2] = __floats2half2_rn(v[2], v[3]);
            }
        }
    }
    __syncthreads();

    // ---- V load (fp32 -> fp16), overlaid on Q buffer ----
    for (int c = tid; c < 2048; c += 384) {
        const int row = c >> 5, ch = c & 31;
        float4 v = *(const float4*)(V + base + (size_t)row * 4096 + ch * 4);
        __half2* dst = (__half2*)&sQV[row * SQH + ch * 4];
        dst[0] = __floats2half2_rn(v.x, v.y);
        dst[1] = __floats2half2_rn(v.z, v.w);
    }
    __syncthreads();

    // ---- O = S @ V: cost-balanced chunk map (chunk c costs c+1) ----
    {
        const int w = tid >> 5, lane = tid & 31;
        const int d0 = lane * 4;
        int clist[2];
        clist[0] = 15 - w;
        clist[1] = (w >= 8) ? (w - 8) : -1;
#pragma unroll
        for (int ci = 0; ci < 2; ci++) {
            const int c = clist[ci];
            if (c < 0) continue;
#pragma unroll
            for (int qq = 0; qq < 4; qq++) {
                const int q = c * 4 + qq;
                float a0 = 0.f, a1 = 0.f, a2 = 0.f, a3 = 0.f;
                for (int kq = 0; kq <= c; kq++) {
                    float2 sa = __half22float2(*(const __half2*)&sS[q * SSH + kq * 4]);
                    float2 sc = __half22float2(*(const __half2*)&sS[q * SSH + kq * 4 + 2]);
                    const float sv[4] = {sa.x, sa.y, sc.x, sc.y};
#pragma unroll
                    for (int r = 0; r < 4; r++) {
                        float2 va = __half22float2(*(const __half2*)&sQV[(kq * 4 + r) * SQH + d0]);
                        float2 vb = __half22float2(*(const __half2*)&sQV[(kq * 4 + r) * SQH + d0 + 2]);
                        a0 = fmaf(sv[r], va.x, a0);
                        a1 = fmaf(sv[r], va.y, a1);
                        a2 = fmaf(sv[r], vb.x, a2);
                        a3 = fmaf(sv[r], vb.y, a3);
                    }
                }
                const size_t go = base + (size_t)q * 4096 + d0;
                *(__half2*)(OH + go)     = __floats2half2_rn(a0, a1);
                *(__half2*)(OH + go + 2) = __floats2half2_rn(a2, a3);
            }
        }
    }
}

// =====================================================================
// launch
// =====================================================================
extern "C" void kernel_launch(void* const* d_in, const int* in_sizes, int n_in,
                              void* d_out, int out_size)
{
    const float* x  = (const float*)d_in[0];
    const float* t  = (const float*)d_in[1];
    const float* Wq = (const float*)d_in[2];
    const float* bq = (const float*)d_in[3];
    const float* Wk = (const float*)d_in[4];
    const float* bk = (const float*)d_in[5];
    const float* Wv = (const float*)d_in[6];
    const float* bv = (const float*)d_in[7];
    const float* Wd = (const float*)d_in[8];
    const float* bd = (const float*)d_in[9];
    const float* Wo = (const float*)d_in[10];
    const float* bo = (const float*)d_in[11];
    float* out = (float*)d_out;

    float *Qb, *Kb, *Vb, *Gb;
    __half *xh, *ah, *wh;
    cudaGetSymbolAddress((void**)&Qb, g_Q);
    cudaGetSymbolAddress((void**)&Kb, g_K);
    cudaGetSymbolAddress((void**)&Vb, g_V);
    cudaGetSymbolAddress((void**)&Gb, g_G);
    cudaGetSymbolAddress((void**)&xh, g_xh);
    cudaGetSymbolAddress((void**)&ah, g_ah);
    cudaGetSymbolAddress((void**)&wh, g_wh);

    const int n4x = MTOT * NE / 4;
    const int n4w = NE * KE / 4;
    conv_h<<<2048, 256>>>(x, xh, n4x);
    conv_w5<<<16384, 256>>>(Wq, Wk, Wv, Wd, Wo, wh, n4w);

    cudaFuncSetAttribute(gemm_f, cudaFuncAttributeMaxDynamicSharedMemorySize, GSMEM);

    // merged Q/K/V/gamma projections (all 1-term; z=3 -> sigmoid epilogue)
    gemm_f<<<dim3(NE / 256, MTOT / 128, 4), 256, GSMEM>>>(
        xh, wh, bq, bk, bv, bd, Qb, Kb, Vb, Gb, /*sigz=*/3);

    // fused attention (2 CTAs/SM, balanced O-phase, writes fp16 plane)
    cudaFuncSetAttribute(attn3, cudaFuncAttributeMaxDynamicSharedMemorySize, A3SMEM);
    attn3<<<1024, 384, A3SMEM>>>(Qb, Kb, Vb, Gb, t, ah);

    // output projection (1-term)
    gemm_f<<<dim3(NE / 256, MTOT / 128, 1), 256, GSMEM>>>(
        ah, wh + 4 * WSL, bo, bo, bo, bo, out, out, out, out, /*sigz=*/-1);
}